// round 11
// baseline (speedup 1.0000x reference)
#include <cuda_runtime.h>

#define DD 24
#define HH 48
#define WW 64
#define NV (DD*HH*WW)        /* 73728 interior voxels */
#define CIN 32
#define COUT 48
#define OHALF 24             /* channels per qkv block (gridDim.y = 2) */

#define TD 6
#define TH 8
#define SROW 68                        /* padded smem row stride (floats) */
#define NROWS ((TD+2)*(TH+2))          /* 80 */
#define NTHR (16*TH*TD)                /* 768 threads */

// scratch (allocation-free rule: __device__ globals)
__device__ float g_q[COUT * NV];
__device__ float g_k[COUT * NV];
__device__ float g_v[COUT * NV];

typedef unsigned long long u64;
__device__ __forceinline__ u64 fma2(u64 a, u64 b, u64 c) {
    u64 d; asm("fma.rn.f32x2 %0,%1,%2,%3;" : "=l"(d) : "l"(a), "l"(b), "l"(c));
    return d;
}
__device__ __forceinline__ u64 add2(u64 a, u64 b) {
    u64 d; asm("add.rn.f32x2 %0,%1,%2;" : "=l"(d) : "l"(a), "l"(b));
    return d;
}
__device__ __forceinline__ float ex2f(float x) {
    float y; asm("ex2.approx.ftz.f32 %0, %1;" : "=f"(y) : "f"(x)); return y;
}
__device__ __forceinline__ float rcpf(float x) {
    float y; asm("rcp.approx.ftz.f32 %0, %1;" : "=f"(y) : "f"(x)); return y;
}

// ---------------------------------------------------------------------------
// Fused QKV: one thread = one voxel pair x 24 channels; packed f32x2 math,
// LDS.128 weights. FULL o-unroll: ptxas gets a wide scheduling window and
// ~128-reg headroom (occupancy is capped at 512 thr/SM by 90 regs anyway)
// to hoist weight loads across iterations.
// ---------------------------------------------------------------------------
__global__ __launch_bounds__(256)
void qkv_kernel(const float* __restrict__ x,
                const float* __restrict__ Wq,
                const float* __restrict__ Wk,
                const float* __restrict__ Wv) {
    __shared__ u64 swq[OHALF * CIN];
    __shared__ u64 swk[OHALF * CIN];
    __shared__ u64 swv[OHALF * CIN];

    const int ob = blockIdx.y * OHALF;
    for (int i = threadIdx.x; i < OHALF * CIN; i += 256) {
        const int gi = ob * CIN + i;
        float a = Wq[gi], b = Wk[gi], c = Wv[gi];
        u64 pa, pb, pc;
        asm("mov.b64 %0,{%1,%1};" : "=l"(pa) : "f"(a));
        asm("mov.b64 %0,{%1,%1};" : "=l"(pb) : "f"(b));
        asm("mov.b64 %0,{%1,%1};" : "=l"(pc) : "f"(c));
        swq[i] = pa; swk[i] = pb; swv[i] = pc;
    }
    __syncthreads();

    const int t = blockIdx.x * 256 + threadIdx.x;   // 0..36863
    const int v0 = t * 2;

    u64 xs[CIN];
    #pragma unroll
    for (int c = 0; c < CIN; c++)
        xs[c] = *(const u64*)(x + c * NV + v0);

    float* __restrict__ gq = g_q + ob * NV + v0;
    float* __restrict__ gk = g_k + ob * NV + v0;
    float* __restrict__ gv = g_v + ob * NV + v0;

    #pragma unroll
    for (int o = 0; o < OHALF; o++) {
        u64 qa = 0, qb = 0, ka = 0, kb = 0, va = 0, vb = 0;
        #pragma unroll
        for (int c = 0; c < CIN; c += 2) {
            const u64 x0 = xs[c], x1 = xs[c + 1];
            const ulonglong2 wq = *(const ulonglong2*)&swq[o * CIN + c];
            const ulonglong2 wk = *(const ulonglong2*)&swk[o * CIN + c];
            const ulonglong2 wv = *(const ulonglong2*)&swv[o * CIN + c];
            qa = fma2(wq.x, x0, qa);  qb = fma2(wq.y, x1, qb);
            ka = fma2(wk.x, x0, ka);  kb = fma2(wk.y, x1, kb);
            va = fma2(wv.x, x0, va);  vb = fma2(wv.y, x1, vb);
        }
        *(u64*)(gq + o * NV) = add2(qa, qb);
        *(u64*)(gk + o * NV) = add2(ka, kb);
        *(u64*)(gv + o * NV) = add2(va, vb);
    }
}

// ---------------------------------------------------------------------------
// Pass 2: per-channel attention, 4 outputs/thread, tile 6x8x64 (768 threads).
// Halo load: div-free, aligned LDG.128; w-halo cols globally OOB -> zeroed.
// ---------------------------------------------------------------------------
template<int GRP>
__device__ __forceinline__ void attn_core(const float* __restrict__ sk,
                                          const float* __restrict__ sv,
                                          const float qs[4],
                                          const float qb[3][4],
                                          int rbase, int w0,
                                          float num[4], float den[4]) {
    #pragma unroll
    for (int kd = 0; kd < 3; kd++) {
        #pragma unroll
        for (int kh = 0; kh < 3; kh++) {
            const int rb = rbase + (kd * (TH + 2) + kh) * SROW + w0;
            const float4 ka = *(const float4*)(sk + rb);
            const float2 kc = *(const float2*)(sk + rb + 4);
            const float4 va = *(const float4*)(sv + rb);
            const float2 vc = *(const float2*)(sv + rb + 4);
            const float kk[6] = {ka.x, ka.y, ka.z, ka.w, kc.x, kc.y};
            const float vv[6] = {va.x, va.y, va.z, va.w, vc.x, vc.y};
            #pragma unroll
            for (int kw = 0; kw < 3; kw++) {
                const int sel = (GRP == 0) ? kw : ((GRP == 1) ? kd : kh);
                #pragma unroll
                for (int wi = 0; wi < 4; wi++) {
                    const float arg = fmaf(qs[wi], kk[wi + kw], qb[sel][wi]);
                    const float ex  = ex2f(arg);
                    den[wi] += ex;
                    num[wi] = fmaf(ex, vv[wi + kw], num[wi]);
                }
            }
        }
    }
}

__global__ __launch_bounds__(NTHR, 2)
void attn_kernel(const float* __restrict__ rel_h,
                 const float* __restrict__ rel_w,
                 const float* __restrict__ rel_d,
                 float* __restrict__ out) {
    __shared__ float sk[NROWS * SROW];
    __shared__ float sv[NROWS * SROW];

    const int o  = blockIdx.z;
    const int d0 = blockIdx.x * TD;
    const int h0 = blockIdx.y * TH;
    const int tid = threadIdx.x + (threadIdx.y << 4) + (threadIdx.z << 7);

    // ---- hoisted gmem loads (overlap with halo fill) ----
    const int w0 = threadIdx.x << 2;
    const int hl = threadIdx.y;
    const int dl = threadIdx.z;
    const int vox0 = ((d0 + dl) * HH + (h0 + hl)) * WW + w0;

    const float4 q4 = *(const float4*)(g_q + o * NV + vox0);
    const int grp = o >> 4, ci = o & 15;
    const float* rel = (grp == 0) ? (rel_d + ci * 3)
                     : (grp == 1) ? (rel_h + ci * 3)
                                  : (rel_w + ci * 3);
    const float b0 = rel[0], b1 = rel[1], b2 = rel[2];

    const float L2E = 1.4426950408889634f;
    float qs[4] = {q4.x * L2E, q4.y * L2E, q4.z * L2E, q4.w * L2E};
    float qb[3][4];
    #pragma unroll
    for (int wi = 0; wi < 4; wi++) {
        qb[0][wi] = qs[wi] * b0;
        qb[1][wi] = qs[wi] * b1;
        qb[2][wi] = qs[wi] * b2;
    }

    // ---- halo load ----
    // w-halo (smem cols 0 and 65) is globally out-of-bounds: always zero.
    if (tid < NROWS * 2) {
        const int r = tid >> 1;
        const int c = (tid & 1) ? 65 : 0;
        sk[r * SROW + c] = 0.f;
        sv[r * SROW + c] = 0.f;
    }
    // main region: row r (0..79), 64 floats per row, aligned LDG.128.
    {
        const int cbase = o * NV;
        const int cx = (tid & 15) << 2;     // w = cx..cx+3
        const int ry = tid >> 4;            // 0..47
        #pragma unroll
        for (int rr = 0; rr < 2; rr++) {
            const int r = ry + rr * 48;
            if (r < NROWS) {
                const int dd = r / (TH + 2);              // mul-shift
                const int hh = r - dd * (TH + 2);
                const int d = d0 + dd - 1;
                const int h = h0 + hh - 1;
                float4 kq = {0.f, 0.f, 0.f, 0.f};
                float4 vq = {0.f, 0.f, 0.f, 0.f};
                if (((unsigned)d < DD) & ((unsigned)h < HH)) {
                    const int g = cbase + (d * HH + h) * WW + cx;
                    kq = *(const float4*)(g_k + g);
                    vq = *(const float4*)(g_v + g);
                }
                const int s = r * SROW + 1 + cx;
                sk[s + 0] = kq.x; sk[s + 1] = kq.y; sk[s + 2] = kq.z; sk[s + 3] = kq.w;
                sv[s + 0] = vq.x; sv[s + 1] = vq.y; sv[s + 2] = vq.z; sv[s + 3] = vq.w;
            }
        }
    }
    __syncthreads();

    const int rbase = (dl * (TH + 2) + hl) * SROW;

    float num[4] = {0.f, 0.f, 0.f, 0.f};
    float den[4] = {0.f, 0.f, 0.f, 0.f};

    if (grp == 0)      attn_core<0>(sk, sv, qs, qb, rbase, w0, num, den);
    else if (grp == 1) attn_core<1>(sk, sv, qs, qb, rbase, w0, num, den);
    else               attn_core<2>(sk, sv, qs, qb, rbase, w0, num, den);

    float4 r;
    r.x = num[0] * rcpf(den[0]);
    r.y = num[1] * rcpf(den[1]);
    r.z = num[2] * rcpf(den[2]);
    r.w = num[3] * rcpf(den[3]);
    *(float4*)(out + o * NV + vox0) = r;
}

extern "C" void kernel_launch(void* const* d_in, const int* in_sizes, int n_in,
                              void* d_out, int out_size) {
    const float* x     = (const float*)d_in[0];
    const float* Wq    = (const float*)d_in[1];
    const float* Wk    = (const float*)d_in[2];
    const float* Wv    = (const float*)d_in[3];
    const float* rel_h = (const float*)d_in[4];
    const float* rel_w = (const float*)d_in[5];
    const float* rel_d = (const float*)d_in[6];
    float* out = (float*)d_out;

    dim3 g1(NV / 2 / 256, 2);
    qkv_kernel<<<g1, 256>>>(x, Wq, Wk, Wv);

    dim3 g2(DD / TD, HH / TH, COUT);
    dim3 b2(16, TH, TD);
    attn_kernel<<<g2, b2>>>(rel_h, rel_w, rel_d, out);
}